// round 4
// baseline (speedup 1.0000x reference)
#include <cuda_runtime.h>
#include <cstdint>

#define D      256
#define NSRC   4096
#define NTOT   8192
#define NBLK   64            // NTOT / 128
#define NPAIRS 2080          // NBLK*(NBLK+1)/2
#define BM     128
#define BK     32
#define EPSV   1e-6

// Scratch (no allocations allowed in kernel_launch)
__device__ float  g_sq[NTOT];
__device__ float  g_colpart[NBLK * D];
__device__ float  g_c;                 // 1 / (16*bandwidth + eps)
__device__ double g_partials[NPAIRS];

// ---------------- packed f32x2 helpers (sm_100+ FFMA2 path) ----------------
__device__ __forceinline__ unsigned long long pack2(float x, float y) {
    unsigned long long r;
    asm("mov.b64 %0, {%1, %2};" : "=l"(r) : "f"(x), "f"(y));
    return r;
}
__device__ __forceinline__ void unpack2(unsigned long long v, float& x, float& y) {
    asm("mov.b64 {%0, %1}, %2;" : "=f"(x), "=f"(y) : "l"(v));
}
__device__ __forceinline__ void fma2(unsigned long long& d,
                                     unsigned long long a,
                                     unsigned long long b) {
    asm("fma.rn.f32x2 %0, %1, %2, %3;" : "=l"(d) : "l"(a), "l"(b), "l"(d));
}

// ---------------------------------------------------------------------------
// Pass 1a: per-row squared norms. One warp per row.
// ---------------------------------------------------------------------------
__global__ void k_sq(const float* __restrict__ src, const float* __restrict__ tgt) {
    int warp = (blockIdx.x * blockDim.x + threadIdx.x) >> 5;
    int lane = threadIdx.x & 31;
    if (warp >= NTOT) return;
    const float* row = (warp < NSRC) ? (src + (size_t)warp * D)
                                     : (tgt + (size_t)(warp - NSRC) * D);
    float s = 0.f;
#pragma unroll
    for (int j = 0; j < D / 32; j++) {
        float v = row[lane + 32 * j];
        s += v * v;
    }
#pragma unroll
    for (int o = 16; o; o >>= 1) s += __shfl_xor_sync(0xffffffffu, s, o);
    if (lane == 0) g_sq[warp] = s;
}

// ---------------------------------------------------------------------------
// Pass 1b: column-sum partials. Block b owns rows [b*128, b*128+128).
// ---------------------------------------------------------------------------
__global__ void k_col(const float* __restrict__ src, const float* __restrict__ tgt) {
    int b = blockIdx.x;
    int d = threadIdx.x;
    const float* base = (b < NBLK / 2) ? (src + (size_t)b * 128 * D)
                                       : (tgt + (size_t)(b - NBLK / 2) * 128 * D);
    float s = 0.f;
#pragma unroll 8
    for (int i = 0; i < 128; i++) s += base[(size_t)i * D + d];
    g_colpart[b * D + d] = s;
}

// ---------------------------------------------------------------------------
// Pass 1c: bandwidth via closed form:
//   sum(L2) = 2*n*sum(sq) - 2*||colsum||^2
// Single block, fixed-order reductions -> deterministic.
// ---------------------------------------------------------------------------
__global__ void k_bw() {
    int d = threadIdx.x;
    double cs = 0.0;
#pragma unroll 8
    for (int b = 0; b < NBLK; b++) cs += (double)g_colpart[b * D + d];
    double ssq_term = cs * cs;
    double sq_sum = 0.0;
    for (int i = d; i < NTOT; i += 256) sq_sum += (double)g_sq[i];

    __shared__ double sh1[256], sh2[256];
    sh1[d] = ssq_term;
    sh2[d] = sq_sum;
    __syncthreads();
    for (int o = 128; o; o >>= 1) {
        if (d < o) { sh1[d] += sh1[d + o]; sh2[d] += sh2[d + o]; }
        __syncthreads();
    }
    if (d == 0) {
        double n     = (double)NTOT;
        double sumL2 = 2.0 * (n * sh2[0] - sh1[0]);
        double bw    = sumL2 / (n * n - n) / 4.0;   // / KERNEL_MUL^(KERNEL_NUM//2)
        g_c = (float)(1.0 / (bw * 16.0 + EPSV));
    }
}

// ---------------------------------------------------------------------------
// Pass 2: triangular tile sweep. CTA = one (bi<=bj) 128x128 tile.
// 8x8 register tile computed as 8x(4 packed f32x2) FFMA2, fused MMD epilogue:
//   L2 = sq_i + sq_j - 2*dot
//   u  = exp(-L2 * c);  K = u + u^2 + u^4 + u^8 + u^16
// Global loads for the next K-slice are prefetched into registers while the
// current slice computes. Sign constant per tile; double accum; no atomics.
// ---------------------------------------------------------------------------
__global__ void __launch_bounds__(256, 2) k_main(const float* __restrict__ src,
                                                 const float* __restrict__ tgt) {
    // decode linear blockIdx -> (bi, bj) with bi <= bj
    int bi = 0, rem = blockIdx.x;
    while (rem >= NBLK - bi) { rem -= NBLK - bi; bi++; }
    int bj = bi + rem;

    const float* A = (bi < NBLK / 2) ? (src + (size_t)bi * 128 * D)
                                     : (tgt + (size_t)(bi - NBLK / 2) * 128 * D);
    const float* B = (bj < NBLK / 2) ? (src + (size_t)bj * 128 * D)
                                     : (tgt + (size_t)(bj - NBLK / 2) * 128 * D);

    __shared__ float As[BK][BM + 4];
    __shared__ float Bs[BK][BM + 4];

    int t  = threadIdx.x;
    int tx = t & 15;        // 0..15 -> col group of 8
    int ty = t >> 4;        // 0..15 -> row group of 8

    unsigned long long acc2[8][4];
#pragma unroll
    for (int i = 0; i < 8; i++)
#pragma unroll
        for (int j = 0; j < 4; j++) acc2[i][j] = 0ull;

    int lr = t >> 3;          // 0..31
    int lc = (t & 7) * 4;     // 0,4,...,28

    // prefetch K-slice 0
    float4 va[4], vb[4];
#pragma unroll
    for (int p = 0; p < 4; p++) {
        int r = p * 32 + lr;
        va[p] = *(const float4*)(A + (size_t)r * D + lc);
        vb[p] = *(const float4*)(B + (size_t)r * D + lc);
    }

    for (int k0 = 0; k0 < D; k0 += BK) {
        // stage prefetched slice into smem
#pragma unroll
        for (int p = 0; p < 4; p++) {
            int r = p * 32 + lr;
            As[lc + 0][r] = va[p].x; As[lc + 1][r] = va[p].y;
            As[lc + 2][r] = va[p].z; As[lc + 3][r] = va[p].w;
            Bs[lc + 0][r] = vb[p].x; Bs[lc + 1][r] = vb[p].y;
            Bs[lc + 2][r] = vb[p].z; Bs[lc + 3][r] = vb[p].w;
        }
        __syncthreads();

        // prefetch next K-slice while computing this one
        if (k0 + BK < D) {
#pragma unroll
            for (int p = 0; p < 4; p++) {
                int r = p * 32 + lr;
                va[p] = *(const float4*)(A + (size_t)r * D + k0 + BK + lc);
                vb[p] = *(const float4*)(B + (size_t)r * D + k0 + BK + lc);
            }
        }

#pragma unroll
        for (int kk = 0; kk < BK; kk++) {
            float a[8], b[8];
            *(float4*)(a)     = *(const float4*)&As[kk][ty * 8];
            *(float4*)(a + 4) = *(const float4*)&As[kk][ty * 8 + 4];
            *(float4*)(b)     = *(const float4*)&Bs[kk][tx * 8];
            *(float4*)(b + 4) = *(const float4*)&Bs[kk][tx * 8 + 4];
            unsigned long long b2[4];
#pragma unroll
            for (int j = 0; j < 4; j++) b2[j] = pack2(b[2 * j], b[2 * j + 1]);
#pragma unroll
            for (int i = 0; i < 8; i++) {
                unsigned long long ad = pack2(a[i], a[i]);
#pragma unroll
                for (int j = 0; j < 4; j++) fma2(acc2[i][j], ad, b2[j]);
            }
        }
        __syncthreads();
    }

    // epilogue
    float c = g_c;
    float sqa[8], sqb[8];
#pragma unroll
    for (int i = 0; i < 8; i++) {
        sqa[i] = g_sq[bi * 128 + ty * 8 + i];
        sqb[i] = g_sq[bj * 128 + tx * 8 + i];
    }
    double tsum = 0.0;
#pragma unroll
    for (int i = 0; i < 8; i++) {
#pragma unroll
        for (int j = 0; j < 4; j++) {
            float d0, d1;
            unpack2(acc2[i][j], d0, d1);
            float L2a = sqa[i] + sqb[2 * j]     - 2.f * d0;
            float L2b = sqa[i] + sqb[2 * j + 1] - 2.f * d1;
            float ua  = __expf(-L2a * c);
            float ub  = __expf(-L2b * c);
            float ua2 = ua * ua, ua4 = ua2 * ua2, ua8 = ua4 * ua4;
            float ub2 = ub * ub, ub4 = ub2 * ub2, ub8 = ub4 * ub4;
            float sa  = ua + ua2 + ua4 + ua8 + ua8 * ua8;
            float sb  = ub + ub2 + ub4 + ub8 + ub8 * ub8;
            tsum += (double)(sa + sb);
        }
    }

    __shared__ double red[256];
    red[t] = tsum;
    __syncthreads();
    for (int o = 128; o; o >>= 1) {
        if (t < o) red[t] += red[t + o];
        __syncthreads();
    }
    if (t == 0) {
        double w   = (bi == bj) ? 1.0 : 2.0;                      // symmetry weight
        double sgn = ((bi < NBLK / 2) == (bj < NBLK / 2)) ? 1.0 : -1.0;
        g_partials[blockIdx.x] = w * sgn * red[0];
    }
}

// ---------------------------------------------------------------------------
// Pass 3: deterministic final reduction -> scalar mean.
// ---------------------------------------------------------------------------
__global__ void k_final(float* __restrict__ out) {
    __shared__ double red[256];
    int t = threadIdx.x;
    double s = 0.0;
    for (int i = t; i < NPAIRS; i += 256) s += g_partials[i];
    red[t] = s;
    __syncthreads();
    for (int o = 128; o; o >>= 1) {
        if (t < o) red[t] += red[t + o];
        __syncthreads();
    }
    if (t == 0) out[0] = (float)(red[0] / ((double)NSRC * (double)NSRC));
}

// ---------------------------------------------------------------------------
extern "C" void kernel_launch(void* const* d_in, const int* in_sizes, int n_in,
                              void* d_out, int out_size) {
    const float* src = (const float*)d_in[0];
    const float* tgt = (const float*)d_in[1];
    (void)in_sizes; (void)n_in; (void)out_size;

    k_sq<<<NTOT / 8, 256>>>(src, tgt);      // 8 warps/block -> 8 rows/block
    k_col<<<NBLK, 256>>>(src, tgt);
    k_bw<<<1, 256>>>();
    k_main<<<NPAIRS, 256>>>(src, tgt);
    k_final<<<1, 256>>>((float*)d_out);
}

// round 11
// speedup vs baseline: 1.4804x; 1.4804x over previous
#include <cuda_runtime.h>
#include <cuda_bf16.h>
#include <cstdint>
#include <cstring>

#define D      256
#define NSRC   4096
#define NTOT   8192
#define NBLK   64            // NTOT / 128
#define NPAIRS 2080          // NBLK*(NBLK+1)/2
#define NCOLB  512           // column-sum partial blocks (16 rows each)
#define EPSV   1e-6
#define KC     64            // K chunk (f32 columns per stage)

// ---- k_main dynamic smem layout ----
#define OFF_SQA    0         // 128 f32
#define OFF_SQB    512       // 128 f32
#define OFF_STAGE0 2048
#define MAT_SZ     16384     // 128 rows x 64 bf16 (128B rows, SW128)
#define STAGE_SZ   (4 * MAT_SZ)                  // A_hi, A_lo, B_hi, B_lo
#define SMEM_SZ    (OFF_STAGE0 + 2 * STAGE_SZ)   // 133120

// Scratch
__device__ float  g_sq[NTOT];
__device__ float  g_colpart[NCOLB * D];
__device__ float  g_c;                 // 1 / (16*bandwidth + eps)
__device__ double g_partials[NPAIRS];

// ========================= helpers =========================
__device__ __forceinline__ uint32_t smem_u32(const void* p) {
    uint32_t a;
    asm("{ .reg .u64 t; cvta.to.shared.u64 t, %1; cvt.u32.u64 %0, t; }"
        : "=r"(a) : "l"(p));
    return a;
}
#define SW128(off) ((off) ^ (((off) >> 3) & 0x70))

#define LDSM_X4(r, a)                                                        \
    asm volatile("ldmatrix.sync.aligned.m8n8.x4.shared.b16 {%0,%1,%2,%3}, [%4];" \
        : "=r"((r)[0]), "=r"((r)[1]), "=r"((r)[2]), "=r"((r)[3]) : "r"(a))

#define MMA_BF16(c, a, b0, b1)                                               \
    asm volatile("mma.sync.aligned.m16n8k16.row.col.f32.bf16.bf16.f32 "      \
        "{%0,%1,%2,%3}, {%4,%5,%6,%7}, {%8,%9}, {%0,%1,%2,%3};"              \
        : "+f"((c)[0]), "+f"((c)[1]), "+f"((c)[2]), "+f"((c)[3])             \
        : "r"((a)[0]), "r"((a)[1]), "r"((a)[2]), "r"((a)[3]),                \
          "r"(b0), "r"(b1))

__device__ __forceinline__ uint32_t b2u(__nv_bfloat162 h) {
    uint32_t u; memcpy(&u, &h, 4); return u;
}

// ---------------------------------------------------------------------------
// Pass 1a: per-row squared norms. One warp per row.
// ---------------------------------------------------------------------------
__global__ void k_sq(const float* __restrict__ src, const float* __restrict__ tgt) {
    int warp = (blockIdx.x * blockDim.x + threadIdx.x) >> 5;
    int lane = threadIdx.x & 31;
    if (warp >= NTOT) return;
    const float* row = (warp < NSRC) ? (src + (size_t)warp * D)
                                     : (tgt + (size_t)(warp - NSRC) * D);
    float s = 0.f;
#pragma unroll
    for (int j = 0; j < D / 32; j++) {
        float v = row[lane + 32 * j];
        s += v * v;
    }
#pragma unroll
    for (int o = 16; o; o >>= 1) s += __shfl_xor_sync(0xffffffffu, s, o);
    if (lane == 0) g_sq[warp] = s;
}

// ---------------------------------------------------------------------------
// Pass 1b: column-sum partials, 16 rows per block.
// ---------------------------------------------------------------------------
__global__ void k_col(const float* __restrict__ src, const float* __restrict__ tgt) {
    int b = blockIdx.x;
    int d = threadIdx.x;
    int g0 = b * 16;
    const float* base = (g0 < NSRC) ? (src + (size_t)g0 * D)
                                    : (tgt + (size_t)(g0 - NSRC) * D);
    float s = 0.f;
#pragma unroll
    for (int i = 0; i < 16; i++) s += base[(size_t)i * D + d];
    g_colpart[b * D + d] = s;
}

// ---------------------------------------------------------------------------
// Pass 1c: bandwidth via closed form: sum(L2) = 2*n*sum(sq) - 2*||colsum||^2
// ---------------------------------------------------------------------------
__global__ void k_bw() {
    int d = threadIdx.x;
    double cs = 0.0;
#pragma unroll 8
    for (int b = 0; b < NCOLB; b++) cs += (double)g_colpart[b * D + d];
    double ssq_term = cs * cs;
    double sq_sum = 0.0;
    for (int i = d; i < NTOT; i += 256) sq_sum += (double)g_sq[i];

    __shared__ double sh1[256], sh2[256];
    sh1[d] = ssq_term;
    sh2[d] = sq_sum;
    __syncthreads();
    for (int o = 128; o; o >>= 1) {
        if (d < o) { sh1[d] += sh1[d + o]; sh2[d] += sh2[d + o]; }
        __syncthreads();
    }
    if (d == 0) {
        double n     = (double)NTOT;
        double sumL2 = 2.0 * (n * sh2[0] - sh1[0]);
        double bw    = sumL2 / (n * n - n) / 4.0;
        g_c = (float)(1.0 / (bw * 16.0 + EPSV));
    }
}

// ---------------------------------------------------------------------------
// Pass 2: split-bf16 HMMA tile kernel (portable mma.sync path).
// CTA = one (bi<=bj) 128x128 tile; 8 warps in 4(M)x2(N); warp tile 32x64.
//   dot_f32(x,y) ~ hi.hi + hi.lo + lo.hi  (3 bf16 m16n8k16 MMAs per frag pair)
// All threads: LDG f32 -> bf16 hi/lo split -> SW128 STS ([idx][k] row-major).
// Double-buffered K chunks (KC=64) with register prefetch of the next chunk.
// Epilogue in registers: L2 = sq_i + sq_j - 2*dot; u=exp(-L2*c);
//   K = u + u^2 + u^4 + u^8 + u^16. Deterministic double reduction.
// ---------------------------------------------------------------------------
__global__ void __launch_bounds__(256, 1) k_main(const float* __restrict__ src,
                                                 const float* __restrict__ tgt) {
    extern __shared__ __align__(1024) char sm[];
    uint32_t sb = smem_u32(sm);

    // decode linear blockIdx -> (bi, bj) with bi <= bj
    int bi = 0, rem = blockIdx.x;
    while (rem >= NBLK - bi) { rem -= NBLK - bi; bi++; }
    int bj = bi + rem;

    const float* A = (bi < NBLK / 2) ? (src + (size_t)bi * 128 * D)
                                     : (tgt + (size_t)(bi - NBLK / 2) * 128 * D);
    const float* B = (bj < NBLK / 2) ? (src + (size_t)bj * 128 * D)
                                     : (tgt + (size_t)(bj - NBLK / 2) * 128 * D);

    int t    = threadIdx.x;
    int l    = t & 31;
    int wid  = t >> 5;
    int wm   = wid >> 1;          // 0..3 -> M offset wm*32
    int wn   = wid & 1;           // 0..1 -> N offset wn*64

    // sq caches
    float* sqa_sm = (float*)(sm + OFF_SQA);
    float* sqb_sm = (float*)(sm + OFF_SQB);
    if (t < 128) sqa_sm[t] = g_sq[bi * 128 + t];
    else         sqb_sm[t - 128] = g_sq[bj * 128 + (t - 128)];

    float acc[2][8][4];
#pragma unroll
    for (int mi = 0; mi < 2; mi++)
#pragma unroll
        for (int ni = 0; ni < 8; ni++)
#pragma unroll
            for (int r = 0; r < 4; r++) acc[mi][ni][r] = 0.f;

    // per-thread load slots: 8 float4 per matrix per chunk
    int row8[8], q8[8];
#pragma unroll
    for (int p = 0; p < 8; p++) {
        int i = t + 256 * p;
        row8[p] = i >> 4;
        q8[p]   = i & 15;
    }

    float4 av[8], bv[8];
#pragma unroll
    for (int p = 0; p < 8; p++) {
        av[p] = *(const float4*)(A + (size_t)row8[p] * D + q8[p] * 4);
        bv[p] = *(const float4*)(B + (size_t)row8[p] * D + q8[p] * 4);
    }

    // ldmatrix lane address components (within a stage matrix)
    //  A: row = rm + (l&15), kbyte = ks*32 + ((l>>4)<<4)
    //  B: n   = nb + (l&7) + ((l>>4)<<3), kbyte = ks*32 + (((l>>3)&1)<<4)
    uint32_t a_lrow = (uint32_t)(l & 15);
    uint32_t a_lkb  = (uint32_t)((l >> 4) << 4);
    uint32_t b_ln   = (uint32_t)((l & 7) + ((l >> 4) << 3));
    uint32_t b_lkb  = (uint32_t)(((l >> 3) & 1) << 4);

    for (int c = 0; c < 4; c++) {
        int s = c & 1;
        char* stg = sm + OFF_STAGE0 + s * STAGE_SZ;

        // convert + store this chunk
#pragma unroll
        for (int p = 0; p < 8; p++) {
            uint32_t off = SW128((uint32_t)(row8[p] * 128 + q8[p] * 8));
            {
                float4 v = av[p];
                __nv_bfloat162 H01 = __floats2bfloat162_rn(v.x, v.y);
                __nv_bfloat162 H23 = __floats2bfloat162_rn(v.z, v.w);
                __nv_bfloat162 L01 = __floats2bfloat162_rn(
                    v.x - __low2float(H01), v.y - __high2float(H01));
                __nv_bfloat162 L23 = __floats2bfloat162_rn(
                    v.z - __low2float(H23), v.w - __high2float(H23));
                *(uint2*)(stg + off)          = make_uint2(b2u(H01), b2u(H23));
                *(uint2*)(stg + MAT_SZ + off) = make_uint2(b2u(L01), b2u(L23));
            }
            {
                float4 v = bv[p];
                __nv_bfloat162 H01 = __floats2bfloat162_rn(v.x, v.y);
                __nv_bfloat162 H23 = __floats2bfloat162_rn(v.z, v.w);
                __nv_bfloat162 L01 = __floats2bfloat162_rn(
                    v.x - __low2float(H01), v.y - __high2float(H01));
                __nv_bfloat162 L23 = __floats2bfloat162_rn(
                    v.z - __low2float(H23), v.w - __high2float(H23));
                *(uint2*)(stg + 2 * MAT_SZ + off) = make_uint2(b2u(H01), b2u(H23));
                *(uint2*)(stg + 3 * MAT_SZ + off) = make_uint2(b2u(L01), b2u(L23));
            }
        }

        // prefetch next chunk (overlaps with MMA below)
        if (c < 3) {
#pragma unroll
            for (int p = 0; p < 8; p++) {
                av[p] = *(const float4*)(A + (size_t)row8[p] * D + (c + 1) * KC + q8[p] * 4);
                bv[p] = *(const float4*)(B + (size_t)row8[p] * D + (c + 1) * KC + q8[p] * 4);
            }
        }
        __syncthreads();

        uint32_t ah_base = sb + OFF_STAGE0 + s * STAGE_SZ;
        uint32_t al_base = ah_base + MAT_SZ;
        uint32_t bh_base = ah_base + 2 * MAT_SZ;
        uint32_t bl_base = ah_base + 3 * MAT_SZ;

#pragma unroll
        for (int ks = 0; ks < 4; ks++) {
            uint32_t kb = (uint32_t)(ks * 32);
            uint32_t aH[2][4], aL[2][4], bH[4][4], bL[4][4];
#pragma unroll
            for (int mi = 0; mi < 2; mi++) {
                uint32_t rowb = (uint32_t)((wm * 32 + mi * 16) + a_lrow) * 128
                              + kb + a_lkb;
                uint32_t offA = SW128(rowb);
                LDSM_X4(aH[mi], ah_base + offA);
                LDSM_X4(aL[mi], al_base + offA);
            }
#pragma unroll
            for (int pr = 0; pr < 4; pr++) {
                uint32_t rowb = (uint32_t)((wn * 64 + pr * 16) + b_ln) * 128
                              + kb + b_lkb;
                uint32_t offB = SW128(rowb);
                LDSM_X4(bH[pr], bh_base + offB);
                LDSM_X4(bL[pr], bl_base + offB);
            }
#pragma unroll
            for (int mi = 0; mi < 2; mi++)
#pragma unroll
                for (int ni = 0; ni < 8; ni++) {
                    int pr = ni >> 1, hf = (ni & 1) * 2;
                    MMA_BF16(acc[mi][ni], aH[mi], bH[pr][hf], bH[pr][hf + 1]);
                    MMA_BF16(acc[mi][ni], aH[mi], bL[pr][hf], bL[pr][hf + 1]);
                    MMA_BF16(acc[mi][ni], aL[mi], bH[pr][hf], bH[pr][hf + 1]);
                }
        }
        __syncthreads();
    }

    // ------------- epilogue (registers -> exp chain -> reduce) -------------
    float cc  = g_c;
    int gid  = l >> 2;
    int tid4 = l & 3;
    double tsum = 0.0;
#pragma unroll
    for (int mi = 0; mi < 2; mi++) {
        int r0 = wm * 32 + mi * 16 + gid;
        float sa0 = sqa_sm[r0];
        float sa1 = sqa_sm[r0 + 8];
#pragma unroll
        for (int ni = 0; ni < 8; ni++) {
            int c0 = wn * 64 + ni * 8 + 2 * tid4;
            float sb0 = sqb_sm[c0];
            float sb1 = sqb_sm[c0 + 1];
            float L2a = sa0 + sb0 - 2.f * acc[mi][ni][0];
            float L2b = sa0 + sb1 - 2.f * acc[mi][ni][1];
            float L2c = sa1 + sb0 - 2.f * acc[mi][ni][2];
            float L2d = sa1 + sb1 - 2.f * acc[mi][ni][3];
            float ua = __expf(-L2a * cc), ub = __expf(-L2b * cc);
            float uc = __expf(-L2c * cc), ud = __expf(-L2d * cc);
            float ua2 = ua * ua, ua4 = ua2 * ua2, ua8 = ua4 * ua4;
            float ub2 = ub * ub, ub4 = ub2 * ub2, ub8 = ub4 * ub4;
            float uc2 = uc * uc, uc4 = uc2 * uc2, uc8 = uc4 * uc4;
            float ud2 = ud * ud, ud4 = ud2 * ud2, ud8 = ud4 * ud4;
            float s1 = (ua + ua2 + ua4 + ua8 + ua8 * ua8)
                     + (ub + ub2 + ub4 + ub8 + ub8 * ub8);
            float s2 = (uc + uc2 + uc4 + uc8 + uc8 * uc8)
                     + (ud + ud2 + ud4 + ud8 + ud8 * ud8);
            tsum += (double)(s1 + s2);
        }
    }

    __syncthreads();
    double* red = (double*)(sm + OFF_STAGE0);
    red[t] = tsum;
    __syncthreads();
    for (int o = 128; o; o >>= 1) {
        if (t < o) red[t] += red[t + o];
        __syncthreads();
    }
    if (t == 0) {
        double w   = (bi == bj) ? 1.0 : 2.0;
        double sgn = ((bi < NBLK / 2) == (bj < NBLK / 2)) ? 1.0 : -1.0;
        g_partials[blockIdx.x] = w * sgn * red[0];
    }
}

// ---------------------------------------------------------------------------
// Pass 3: deterministic final reduction -> scalar mean.
// ---------------------------------------------------------------------------
__global__ void k_final(float* __restrict__ out) {
    __shared__ double red[256];
    int t = threadIdx.x;
    double s = 0.0;
    for (int i = t; i < NPAIRS; i += 256) s += g_partials[i];
    red[t] = s;
    __syncthreads();
    for (int o = 128; o; o >>= 1) {
        if (t < o) red[t] += red[t + o];
        __syncthreads();
    }
    if (t == 0) out[0] = (float)(red[0] / ((double)NSRC * (double)NSRC));
}

// ---------------------------------------------------------------------------
extern "C" void kernel_launch(void* const* d_in, const int* in_sizes, int n_in,
                              void* d_out, int out_size) {
    const float* src = (const float*)d_in[0];
    const float* tgt = (const float*)d_in[1];
    (void)in_sizes; (void)n_in; (void)out_size;

    cudaFuncSetAttribute(k_main, cudaFuncAttributeMaxDynamicSharedMemorySize, SMEM_SZ);

    k_sq<<<NTOT / 8, 256>>>(src, tgt);
    k_col<<<NCOLB, 256>>>(src, tgt);
    k_bw<<<1, 256>>>();
    k_main<<<NPAIRS, 256, SMEM_SZ>>>(src, tgt);
    k_final<<<1, 256>>>((float*)d_out);
}